// round 7
// baseline (speedup 1.0000x reference)
#include <cuda_runtime.h>
#include <cuda_bf16.h>
#include <cstdint>

#define N_NODES 50000
#define N_EDGES 1600000
#define C 128
#define E_TOT (N_EDGES + N_NODES)
#define NEG_SLOPE 0.2f
#define NEG_INF (-1e30f)
#define NBLK 49            // ceil(50000/1024)
#define NB 16              // nodes per block in GEMMs (50000 % 16 == 0)
#define GEMM_BLKS (N_NODES / NB)   // 3125
#define HIST_BLKS 4096
#define XS_STRIDE 20       // floats per smem row (80B, 16B-aligned)

// -------- scratch (no device allocs allowed) --------
__device__ float g_h[(size_t)N_NODES * C];
__device__ float g_es[N_NODES];
__device__ float g_ed[N_NODES];
__device__ int   g_deg[N_NODES];
__device__ int   g_off[N_NODES + 1];
__device__ int   g_cursor[N_NODES];
__device__ int   g_adj[E_TOT];
__device__ int   g_bsum[NBLK + 1];

__device__ __forceinline__ float lrelu(float x) {
    return x > 0.f ? x : NEG_SLOPE * x;
}

// ---- merged: GEMM blocks + histogram blocks in one launch ----
__global__ void __launch_bounds__(128) k_gemm_hist(
        const float* __restrict__ x, const float* __restrict__ W,
        const float* __restrict__ a_src, const float* __restrict__ a_dst,
        const int* __restrict__ ei) {
    if (blockIdx.x >= GEMM_BLKS) {
        // -------- histogram part (independent of GEMM) --------
        int tid = (blockIdx.x - GEMM_BLKS) * 128 + threadIdx.x;
        int stride = HIST_BLKS * 128;
        for (int e = tid; e < E_TOT; e += stride) {
            int d = (e < N_EDGES) ? ei[N_EDGES + e] : (e - N_EDGES);
            atomicAdd(&g_deg[d], 1);
        }
        return;
    }
    // -------- GEMM part: h = x@W for NB nodes, fused e_src/e_dst --------
    int nb = blockIdx.x * NB;
    int c = threadIdx.x;
    __shared__ float xs[C][XS_STRIDE];   // transposed tile: xs[k][i]
#pragma unroll
    for (int i = 0; i < NB; i++)
        xs[c][i] = x[(size_t)(nb + i) * C + c];
    __syncthreads();

    float acc[NB];
#pragma unroll
    for (int i = 0; i < NB; i++) acc[i] = 0.f;
#pragma unroll 4
    for (int k = 0; k < C; k++) {
        float w = W[k * C + c];
        const float4 a0 = *(const float4*)&xs[k][0];
        const float4 a1 = *(const float4*)&xs[k][4];
        const float4 a2 = *(const float4*)&xs[k][8];
        const float4 a3 = *(const float4*)&xs[k][12];
        acc[0]  = fmaf(a0.x, w, acc[0]);  acc[1]  = fmaf(a0.y, w, acc[1]);
        acc[2]  = fmaf(a0.z, w, acc[2]);  acc[3]  = fmaf(a0.w, w, acc[3]);
        acc[4]  = fmaf(a1.x, w, acc[4]);  acc[5]  = fmaf(a1.y, w, acc[5]);
        acc[6]  = fmaf(a1.z, w, acc[6]);  acc[7]  = fmaf(a1.w, w, acc[7]);
        acc[8]  = fmaf(a2.x, w, acc[8]);  acc[9]  = fmaf(a2.y, w, acc[9]);
        acc[10] = fmaf(a2.z, w, acc[10]); acc[11] = fmaf(a2.w, w, acc[11]);
        acc[12] = fmaf(a3.x, w, acc[12]); acc[13] = fmaf(a3.y, w, acc[13]);
        acc[14] = fmaf(a3.z, w, acc[14]); acc[15] = fmaf(a3.w, w, acc[15]);
    }
#pragma unroll
    for (int i = 0; i < NB; i++)
        g_h[(size_t)(nb + i) * C + c] = acc[i];

    // fused attention dot products
    float as = a_src[c], ad = a_dst[c];
    __shared__ float rs[NB][4], rd[NB][4];
    int lane = c & 31, wp = c >> 5;
#pragma unroll
    for (int i = 0; i < NB; i++) {
        float ps = acc[i] * as;
        float pd = acc[i] * ad;
#pragma unroll
        for (int o = 16; o > 0; o >>= 1) {
            ps += __shfl_down_sync(0xffffffffu, ps, o);
            pd += __shfl_down_sync(0xffffffffu, pd, o);
        }
        if (lane == 0) { rs[i][wp] = ps; rd[i][wp] = pd; }
    }
    __syncthreads();
    if (c < NB) {
        g_es[nb + c] = rs[c][0] + rs[c][1] + rs[c][2] + rs[c][3];
        g_ed[nb + c] = rd[c][0] + rd[c][1] + rd[c][2] + rd[c][3];
    }
}

__global__ void k_zero() {
    int i = blockIdx.x * blockDim.x + threadIdx.x;
    if (i < N_NODES) g_deg[i] = 0;
}

// ---- scan phase 1: per-block exclusive scan + block sums ----
__global__ void k_scan1() {
    int b = blockIdx.x, tid = threadIdx.x;
    int idx = b * 1024 + tid;
    int v = (idx < N_NODES) ? g_deg[idx] : 0;
    int lane = tid & 31, wp = tid >> 5;
    int val = v;
#pragma unroll
    for (int o = 1; o < 32; o <<= 1) {
        int t = __shfl_up_sync(0xffffffffu, val, o);
        if (lane >= o) val += t;
    }
    __shared__ int wsum[32];
    if (lane == 31) wsum[wp] = val;
    __syncthreads();
    if (wp == 0) {
        int s = wsum[lane];
#pragma unroll
        for (int o = 1; o < 32; o <<= 1) {
            int t = __shfl_up_sync(0xffffffffu, s, o);
            if (lane >= o) s += t;
        }
        wsum[lane] = s;
    }
    __syncthreads();
    int incl = val + (wp ? wsum[wp - 1] : 0);
    if (idx < N_NODES) g_off[idx] = incl - v;
    if (tid == 1023) g_bsum[b] = incl;
}

__global__ void k_scan2() {
    __shared__ int s[64];
    int tid = threadIdx.x;
    s[tid] = (tid < NBLK) ? g_bsum[tid] : 0;
    __syncthreads();
    if (tid == 0) {
        int acc = 0;
        for (int i = 0; i < NBLK; i++) { int t = s[i]; s[i] = acc; acc += t; }
        s[NBLK] = acc;
    }
    __syncthreads();
    if (tid <= NBLK) g_bsum[tid] = s[tid];
}

__global__ void k_scan3() {
    int b = blockIdx.x, tid = threadIdx.x;
    int idx = b * 1024 + tid;
    if (idx < N_NODES) {
        int o = g_off[idx] + g_bsum[b];
        g_off[idx] = o;
        g_cursor[idx] = o;
    }
    if (idx == 0) g_off[N_NODES] = g_bsum[NBLK];
}

__global__ void k_fill(const int* __restrict__ ei) {
    int e = blockIdx.x * blockDim.x + threadIdx.x;
    if (e >= E_TOT) return;
    int s, d;
    if (e < N_EDGES) { s = ei[e]; d = ei[N_EDGES + e]; }
    else             { s = e - N_EDGES; d = s; }
    int pos = atomicAdd(&g_cursor[d], 1);
    g_adj[pos] = s;
}

// ---- fused softmax + aggregation: 1 warp per node, float4 lanes ----
__global__ void k_gather(const float* __restrict__ b_gat, float* __restrict__ zout) {
    int wp = threadIdx.x >> 5, lane = threadIdx.x & 31;
    int n = blockIdx.x * 4 + wp;
    int off = g_off[n];
    int deg = g_off[n + 1] - off;
    float edn = g_ed[n];

    float mt = NEG_INF, st = 0.f;
    for (int j = lane; j < deg; j += 32) {
        float l = lrelu(g_es[g_adj[off + j]] + edn);
        if (l > mt) { st *= __expf(mt - l); mt = l; }
        st += __expf(l - mt);
    }
#pragma unroll
    for (int o = 16; o > 0; o >>= 1) {
        float mo = __shfl_xor_sync(0xffffffffu, mt, o);
        float so = __shfl_xor_sync(0xffffffffu, st, o);
        float pm = fmaxf(mt, mo);
        float a = (mt > NEG_INF) ? st * __expf(mt - pm) : 0.f;
        float b = (mo > NEG_INF) ? so * __expf(mo - pm) : 0.f;
        mt = pm; st = a + b;
    }
    float inv = 1.f / st;

    float4 acc = make_float4(0.f, 0.f, 0.f, 0.f);
    for (int base = 0; base < deg; base += 32) {
        int j = base + lane;
        int sj = 0; float cj = 0.f;
        if (j < deg) {
            sj = g_adj[off + j];
            cj = __expf(lrelu(g_es[sj] + edn) - mt);
        }
        int lim = min(32, deg - base);
#pragma unroll 4
        for (int it = 0; it < lim; it++) {
            int s    = __shfl_sync(0xffffffffu, sj, it);
            float cf = __shfl_sync(0xffffffffu, cj, it);
            float4 v = *(const float4*)(g_h + (size_t)s * C + lane * 4);
            acc.x = fmaf(cf, v.x, acc.x);
            acc.y = fmaf(cf, v.y, acc.y);
            acc.z = fmaf(cf, v.z, acc.z);
            acc.w = fmaf(cf, v.w, acc.w);
        }
    }
    float4 bg = *(const float4*)(b_gat + lane * 4);
    float4 o4 = make_float4(acc.x * inv + bg.x, acc.y * inv + bg.y,
                            acc.z * inv + bg.z, acc.w * inv + bg.w);
    *(float4*)(zout + (size_t)n * C + lane * 4) = o4;
}

// ---- decode: recon = tanh(z @ Wd + bd), NB nodes per block ----
__global__ void __launch_bounds__(128) k_decode(
        const float* __restrict__ Wd, const float* __restrict__ bd,
        float* __restrict__ out) {
    int nb = blockIdx.x * NB;
    int c = threadIdx.x;
    __shared__ float zs[C][XS_STRIDE];
    const float* zbase = out + (size_t)N_NODES * C;
#pragma unroll
    for (int i = 0; i < NB; i++)
        zs[c][i] = zbase[(size_t)(nb + i) * C + c];
    __syncthreads();

    float b = bd[c];
    float acc[NB];
#pragma unroll
    for (int i = 0; i < NB; i++) acc[i] = b;
#pragma unroll 4
    for (int k = 0; k < C; k++) {
        float w = Wd[k * C + c];
        const float4 a0 = *(const float4*)&zs[k][0];
        const float4 a1 = *(const float4*)&zs[k][4];
        const float4 a2 = *(const float4*)&zs[k][8];
        const float4 a3 = *(const float4*)&zs[k][12];
        acc[0]  = fmaf(a0.x, w, acc[0]);  acc[1]  = fmaf(a0.y, w, acc[1]);
        acc[2]  = fmaf(a0.z, w, acc[2]);  acc[3]  = fmaf(a0.w, w, acc[3]);
        acc[4]  = fmaf(a1.x, w, acc[4]);  acc[5]  = fmaf(a1.y, w, acc[5]);
        acc[6]  = fmaf(a1.z, w, acc[6]);  acc[7]  = fmaf(a1.w, w, acc[7]);
        acc[8]  = fmaf(a2.x, w, acc[8]);  acc[9]  = fmaf(a2.y, w, acc[9]);
        acc[10] = fmaf(a2.z, w, acc[10]); acc[11] = fmaf(a2.w, w, acc[11]);
        acc[12] = fmaf(a3.x, w, acc[12]); acc[13] = fmaf(a3.y, w, acc[13]);
        acc[14] = fmaf(a3.z, w, acc[14]); acc[15] = fmaf(a3.w, w, acc[15]);
    }
#pragma unroll
    for (int i = 0; i < NB; i++)
        out[(size_t)(nb + i) * C + c] = tanhf(acc[i]);
}

extern "C" void kernel_launch(void* const* d_in, const int* in_sizes, int n_in,
                              void* d_out, int out_size) {
    const float* x     = (const float*)d_in[0];
    const int*   ei    = (const int*)d_in[1];     // int32 (JAX x64 off)
    const float* W     = (const float*)d_in[2];
    const float* a_src = (const float*)d_in[3];
    const float* a_dst = (const float*)d_in[4];
    const float* b_gat = (const float*)d_in[5];
    const float* Wd    = (const float*)d_in[6];
    const float* bd    = (const float*)d_in[7];
    float* out  = (float*)d_out;
    float* zout = out + (size_t)N_NODES * C;

    k_zero<<<(N_NODES + 255) / 256, 256>>>();
    k_gemm_hist<<<GEMM_BLKS + HIST_BLKS, 128>>>(x, W, a_src, a_dst, ei);
    k_scan1<<<NBLK, 1024>>>();
    k_scan2<<<1, 64>>>();
    k_scan3<<<NBLK, 1024>>>();
    {
        int threads = 256;
        int eblocks = (E_TOT + threads - 1) / threads;
        k_fill<<<eblocks, threads>>>(ei);
    }
    k_gather<<<N_NODES / 4, 128>>>(b_gat, zout);
    k_decode<<<N_NODES / NB, 128>>>(Wd, bd, out);
}

// round 9
// speedup vs baseline: 1.4021x; 1.4021x over previous
#include <cuda_runtime.h>
#include <cuda_bf16.h>
#include <cstdint>

#define N_NODES 50000
#define N_EDGES 1600000
#define C 128
#define E_TOT (N_EDGES + N_NODES)
#define NEG_SLOPE 0.2f
#define NEG_INF (-1e30f)
#define NBLK 49            // ceil(50000/1024)
#define NB 8               // nodes per block in GEMMs (50000 % 8 == 0)
#define GEMM_BLKS (N_NODES / NB)   // 6250
#define HIST_BLKS 2048

// -------- scratch (no device allocs allowed) --------
__device__ float g_h[(size_t)N_NODES * C];
__device__ float g_es[N_NODES];
__device__ float g_ed[N_NODES];
__device__ int   g_deg[N_NODES];
__device__ int   g_off[N_NODES + 1];
__device__ int   g_cursor[N_NODES];
__device__ int   g_adj[E_TOT];
__device__ int   g_bsum[NBLK + 1];

__device__ __forceinline__ float lrelu(float x) {
    return x > 0.f ? x : NEG_SLOPE * x;
}

// ---- merged: GEMM blocks (R5 NB=8 body, unchanged) + histogram blocks ----
__global__ void k_gemm_hist(const float* __restrict__ x, const float* __restrict__ W,
                            const float* __restrict__ a_src, const float* __restrict__ a_dst,
                            const int* __restrict__ ei) {
    if (blockIdx.x >= GEMM_BLKS) {
        // -------- histogram part (independent of GEMM) --------
        int tid = (blockIdx.x - GEMM_BLKS) * 128 + threadIdx.x;
        int stride = HIST_BLKS * 128;
        for (int e = tid; e < E_TOT; e += stride) {
            int d = (e < N_EDGES) ? ei[N_EDGES + e] : (e - N_EDGES);
            atomicAdd(&g_deg[d], 1);
        }
        return;
    }
    // -------- GEMM part: h = x@W for 8 nodes, fused e_src/e_dst --------
    int nb = blockIdx.x * NB;
    int c = threadIdx.x;
    __shared__ float xs[NB][C];
#pragma unroll
    for (int i = 0; i < NB; i++)
        xs[i][c] = x[(size_t)(nb + i) * C + c];
    __syncthreads();
    float acc[NB];
#pragma unroll
    for (int i = 0; i < NB; i++) acc[i] = 0.f;
#pragma unroll 4
    for (int k = 0; k < C; k++) {
        float w = W[k * C + c];
#pragma unroll
        for (int i = 0; i < NB; i++)
            acc[i] = fmaf(xs[i][k], w, acc[i]);
    }
#pragma unroll
    for (int i = 0; i < NB; i++)
        g_h[(size_t)(nb + i) * C + c] = acc[i];

    float as = a_src[c], ad = a_dst[c];
    __shared__ float rs[NB][4], rd[NB][4];
    int lane = c & 31, wp = c >> 5;
#pragma unroll
    for (int i = 0; i < NB; i++) {
        float ps = acc[i] * as;
        float pd = acc[i] * ad;
#pragma unroll
        for (int o = 16; o > 0; o >>= 1) {
            ps += __shfl_down_sync(0xffffffffu, ps, o);
            pd += __shfl_down_sync(0xffffffffu, pd, o);
        }
        if (lane == 0) { rs[i][wp] = ps; rd[i][wp] = pd; }
    }
    __syncthreads();
    if (c < NB) {
        g_es[nb + c] = rs[c][0] + rs[c][1] + rs[c][2] + rs[c][3];
        g_ed[nb + c] = rd[c][0] + rd[c][1] + rd[c][2] + rd[c][3];
    }
}

__global__ void k_zero() {
    int i = blockIdx.x * blockDim.x + threadIdx.x;
    if (i < N_NODES) g_deg[i] = 0;
}

// ---- scan phase 1: per-block exclusive scan + block sums ----
__global__ void k_scan1() {
    int b = blockIdx.x, tid = threadIdx.x;
    int idx = b * 1024 + tid;
    int v = (idx < N_NODES) ? g_deg[idx] : 0;
    int lane = tid & 31, wp = tid >> 5;
    int val = v;
#pragma unroll
    for (int o = 1; o < 32; o <<= 1) {
        int t = __shfl_up_sync(0xffffffffu, val, o);
        if (lane >= o) val += t;
    }
    __shared__ int wsum[32];
    if (lane == 31) wsum[wp] = val;
    __syncthreads();
    if (wp == 0) {
        int s = wsum[lane];
#pragma unroll
        for (int o = 1; o < 32; o <<= 1) {
            int t = __shfl_up_sync(0xffffffffu, s, o);
            if (lane >= o) s += t;
        }
        wsum[lane] = s;
    }
    __syncthreads();
    int incl = val + (wp ? wsum[wp - 1] : 0);
    if (idx < N_NODES) g_off[idx] = incl - v;        // local exclusive
    if (tid == 1023) g_bsum[b] = incl;               // raw block total
}

// ---- scan phase 3 (scan2 folded in): per-block carry + publish cursors ----
__global__ void k_scan3() {
    __shared__ int s_carry;
    int b = blockIdx.x, tid = threadIdx.x;
    if (tid == 0) {
        int acc = 0;
        for (int i = 0; i < b; i++) acc += g_bsum[i];   // prefix of raw totals
        s_carry = acc;
    }
    __syncthreads();
    int carry = s_carry;
    int idx = b * 1024 + tid;
    if (idx < N_NODES) {
        int o = g_off[idx] + carry;
        g_off[idx] = o;
        g_cursor[idx] = o;
    }
    if (b == NBLK - 1 && tid == 1023) {
        g_off[N_NODES] = carry + g_bsum[NBLK - 1];     // grand total (= E_TOT)
    }
}

__global__ void k_fill(const int* __restrict__ ei) {
    int e = blockIdx.x * blockDim.x + threadIdx.x;
    if (e >= E_TOT) return;
    int s, d;
    if (e < N_EDGES) { s = ei[e]; d = ei[N_EDGES + e]; }
    else             { s = e - N_EDGES; d = s; }
    int pos = atomicAdd(&g_cursor[d], 1);
    g_adj[pos] = s;
}

// ---- fused softmax + aggregation: 1 warp per node, float4 lanes ----
__global__ void k_gather(const float* __restrict__ b_gat, float* __restrict__ zout) {
    int wp = threadIdx.x >> 5, lane = threadIdx.x & 31;
    int n = blockIdx.x * 4 + wp;
    int off = g_off[n];
    int deg = g_off[n + 1] - off;
    float edn = g_ed[n];

    float mt = NEG_INF, st = 0.f;
    for (int j = lane; j < deg; j += 32) {
        float l = lrelu(g_es[g_adj[off + j]] + edn);
        if (l > mt) { st *= __expf(mt - l); mt = l; }
        st += __expf(l - mt);
    }
#pragma unroll
    for (int o = 16; o > 0; o >>= 1) {
        float mo = __shfl_xor_sync(0xffffffffu, mt, o);
        float so = __shfl_xor_sync(0xffffffffu, st, o);
        float pm = fmaxf(mt, mo);
        float a = (mt > NEG_INF) ? st * __expf(mt - pm) : 0.f;
        float b = (mo > NEG_INF) ? so * __expf(mo - pm) : 0.f;
        mt = pm; st = a + b;
    }
    float inv = 1.f / st;

    float4 acc = make_float4(0.f, 0.f, 0.f, 0.f);
    for (int base = 0; base < deg; base += 32) {
        int j = base + lane;
        int sj = 0; float cj = 0.f;
        if (j < deg) {
            sj = g_adj[off + j];
            cj = __expf(lrelu(g_es[sj] + edn) - mt);
        }
        int lim = min(32, deg - base);
#pragma unroll 4
        for (int it = 0; it < lim; it++) {
            int s    = __shfl_sync(0xffffffffu, sj, it);
            float cf = __shfl_sync(0xffffffffu, cj, it);
            float4 v = *(const float4*)(g_h + (size_t)s * C + lane * 4);
            acc.x = fmaf(cf, v.x, acc.x);
            acc.y = fmaf(cf, v.y, acc.y);
            acc.z = fmaf(cf, v.z, acc.z);
            acc.w = fmaf(cf, v.w, acc.w);
        }
    }
    float4 bg = *(const float4*)(b_gat + lane * 4);
    float4 o4 = make_float4(acc.x * inv + bg.x, acc.y * inv + bg.y,
                            acc.z * inv + bg.z, acc.w * inv + bg.w);
    *(float4*)(zout + (size_t)n * C + lane * 4) = o4;
}

// ---- decode: recon = tanh(z @ Wd + bd), 8 nodes per block (R5 body) ----
__global__ void k_decode(const float* __restrict__ Wd, const float* __restrict__ bd,
                         float* __restrict__ out) {
    int nb = blockIdx.x * NB;
    int c = threadIdx.x;
    __shared__ float zs[NB][C];
    const float* zbase = out + (size_t)N_NODES * C;
#pragma unroll
    for (int i = 0; i < NB; i++)
        zs[i][c] = zbase[(size_t)(nb + i) * C + c];
    __syncthreads();
    float b = bd[c];
    float acc[NB];
#pragma unroll
    for (int i = 0; i < NB; i++) acc[i] = b;
#pragma unroll 4
    for (int k = 0; k < C; k++) {
        float w = Wd[k * C + c];
#pragma unroll
        for (int i = 0; i < NB; i++)
            acc[i] = fmaf(zs[i][k], w, acc[i]);
    }
#pragma unroll
    for (int i = 0; i < NB; i++)
        out[(size_t)(nb + i) * C + c] = tanhf(acc[i]);
}

extern "C" void kernel_launch(void* const* d_in, const int* in_sizes, int n_in,
                              void* d_out, int out_size) {
    const float* x     = (const float*)d_in[0];
    const int*   ei    = (const int*)d_in[1];     // int32 (JAX x64 off)
    const float* W     = (const float*)d_in[2];
    const float* a_src = (const float*)d_in[3];
    const float* a_dst = (const float*)d_in[4];
    const float* b_gat = (const float*)d_in[5];
    const float* Wd    = (const float*)d_in[6];
    const float* bd    = (const float*)d_in[7];
    float* out  = (float*)d_out;
    float* zout = out + (size_t)N_NODES * C;

    k_zero<<<(N_NODES + 255) / 256, 256>>>();
    k_gemm_hist<<<GEMM_BLKS + HIST_BLKS, C>>>(x, W, a_src, a_dst, ei);
    k_scan1<<<NBLK, 1024>>>();
    k_scan3<<<NBLK, 1024>>>();
    {
        int threads = 256;
        int eblocks = (E_TOT + threads - 1) / threads;
        k_fill<<<eblocks, threads>>>(ei);
    }
    k_gather<<<N_NODES / 4, 128>>>(b_gat, zout);
    k_decode<<<N_NODES / NB, C>>>(Wd, bd, out);
}

// round 10
// speedup vs baseline: 1.4265x; 1.0174x over previous
#include <cuda_runtime.h>
#include <cuda_bf16.h>
#include <cstdint>

#define N_NODES 50000
#define N_EDGES 1600000
#define C 128
#define E_TOT (N_EDGES + N_NODES)
#define NEG_SLOPE 0.2f
#define NEG_INF (-1e30f)
#define NBLK 49            // ceil(50000/1024)
#define NB 8               // nodes per block in GEMMs (50000 % 8 == 0)
#define GEMM_BLKS (N_NODES / NB)   // 6250
#define HIST_BLKS 2048

// -------- scratch (no device allocs allowed) --------
__device__ float g_h[(size_t)N_NODES * C];
__device__ float g_es[N_NODES];
__device__ float g_ed[N_NODES];
__device__ int   g_deg[N_NODES];
__device__ int   g_off[N_NODES + 1];
__device__ int   g_cursor[N_NODES];
__device__ int   g_adj[E_TOT];
__device__ int   g_bsum[NBLK + 1];

__device__ __forceinline__ float lrelu(float x) {
    return x > 0.f ? x : NEG_SLOPE * x;
}

// ---- merged: GEMM blocks (NB=8, transposed float4 smem reads) + histogram ----
__global__ void k_gemm_hist(const float* __restrict__ x, const float* __restrict__ W,
                            const float* __restrict__ a_src, const float* __restrict__ a_dst,
                            const int* __restrict__ ei) {
    if (blockIdx.x >= GEMM_BLKS) {
        // -------- histogram part (independent of GEMM) --------
        int tid = (blockIdx.x - GEMM_BLKS) * 128 + threadIdx.x;
        int stride = HIST_BLKS * 128;
        for (int e = tid; e < E_TOT; e += stride) {
            int d = (e < N_EDGES) ? ei[N_EDGES + e] : (e - N_EDGES);
            atomicAdd(&g_deg[d], 1);
        }
        return;
    }
    // -------- GEMM part: h = x@W for 8 nodes, fused e_src/e_dst --------
    int nb = blockIdx.x * NB;
    int c = threadIdx.x;
    __shared__ float xs[C][NB];          // transposed: xs[k][i], rows 32B
#pragma unroll
    for (int i = 0; i < NB; i++)
        xs[c][i] = x[(size_t)(nb + i) * C + c];
    __syncthreads();
    float acc[NB];
#pragma unroll
    for (int i = 0; i < NB; i++) acc[i] = 0.f;
#pragma unroll 4
    for (int k = 0; k < C; k++) {
        float w = W[k * C + c];
        const float4 a0 = *(const float4*)&xs[k][0];   // broadcast LDS.128
        const float4 a1 = *(const float4*)&xs[k][4];
        acc[0] = fmaf(a0.x, w, acc[0]);  acc[1] = fmaf(a0.y, w, acc[1]);
        acc[2] = fmaf(a0.z, w, acc[2]);  acc[3] = fmaf(a0.w, w, acc[3]);
        acc[4] = fmaf(a1.x, w, acc[4]);  acc[5] = fmaf(a1.y, w, acc[5]);
        acc[6] = fmaf(a1.z, w, acc[6]);  acc[7] = fmaf(a1.w, w, acc[7]);
    }
#pragma unroll
    for (int i = 0; i < NB; i++)
        g_h[(size_t)(nb + i) * C + c] = acc[i];

    float as = a_src[c], ad = a_dst[c];
    __shared__ float rs[NB][4], rd[NB][4];
    int lane = c & 31, wp = c >> 5;
#pragma unroll
    for (int i = 0; i < NB; i++) {
        float ps = acc[i] * as;
        float pd = acc[i] * ad;
#pragma unroll
        for (int o = 16; o > 0; o >>= 1) {
            ps += __shfl_down_sync(0xffffffffu, ps, o);
            pd += __shfl_down_sync(0xffffffffu, pd, o);
        }
        if (lane == 0) { rs[i][wp] = ps; rd[i][wp] = pd; }
    }
    __syncthreads();
    if (c < NB) {
        g_es[nb + c] = rs[c][0] + rs[c][1] + rs[c][2] + rs[c][3];
        g_ed[nb + c] = rd[c][0] + rd[c][1] + rd[c][2] + rd[c][3];
    }
}

__global__ void k_zero() {
    int i = blockIdx.x * blockDim.x + threadIdx.x;
    if (i < N_NODES) g_deg[i] = 0;
}

// ---- scan phase 1: per-block exclusive scan + block sums ----
__global__ void k_scan1() {
    int b = blockIdx.x, tid = threadIdx.x;
    int idx = b * 1024 + tid;
    int v = (idx < N_NODES) ? g_deg[idx] : 0;
    int lane = tid & 31, wp = tid >> 5;
    int val = v;
#pragma unroll
    for (int o = 1; o < 32; o <<= 1) {
        int t = __shfl_up_sync(0xffffffffu, val, o);
        if (lane >= o) val += t;
    }
    __shared__ int wsum[32];
    if (lane == 31) wsum[wp] = val;
    __syncthreads();
    if (wp == 0) {
        int s = wsum[lane];
#pragma unroll
        for (int o = 1; o < 32; o <<= 1) {
            int t = __shfl_up_sync(0xffffffffu, s, o);
            if (lane >= o) s += t;
        }
        wsum[lane] = s;
    }
    __syncthreads();
    int incl = val + (wp ? wsum[wp - 1] : 0);
    if (idx < N_NODES) g_off[idx] = incl - v;        // local exclusive
    if (tid == 1023) g_bsum[b] = incl;               // raw block total
}

// ---- scan phase 3 (scan2 folded in): per-block carry + publish cursors ----
__global__ void k_scan3() {
    __shared__ int s_carry;
    int b = blockIdx.x, tid = threadIdx.x;
    if (tid == 0) {
        int acc = 0;
        for (int i = 0; i < b; i++) acc += g_bsum[i];
        s_carry = acc;
    }
    __syncthreads();
    int carry = s_carry;
    int idx = b * 1024 + tid;
    if (idx < N_NODES) {
        int o = g_off[idx] + carry;
        g_off[idx] = o;
        g_cursor[idx] = o;
    }
    if (b == NBLK - 1 && tid == 1023) {
        g_off[N_NODES] = carry + g_bsum[NBLK - 1];
    }
}

__global__ void k_fill(const int* __restrict__ ei) {
    int e = blockIdx.x * blockDim.x + threadIdx.x;
    if (e >= E_TOT) return;
    int s, d;
    if (e < N_EDGES) { s = ei[e]; d = ei[N_EDGES + e]; }
    else             { s = e - N_EDGES; d = s; }
    int pos = atomicAdd(&g_cursor[d], 1);
    g_adj[pos] = s;
}

// ---- fused softmax + aggregation: 1 warp per node, float4 lanes ----
__global__ void k_gather(const float* __restrict__ b_gat, float* __restrict__ zout) {
    int wp = threadIdx.x >> 5, lane = threadIdx.x & 31;
    int n = blockIdx.x * 4 + wp;
    int off = g_off[n];
    int deg = g_off[n + 1] - off;
    float edn = g_ed[n];

    float mt = NEG_INF, st = 0.f;
    for (int j = lane; j < deg; j += 32) {
        float l = lrelu(g_es[g_adj[off + j]] + edn);
        if (l > mt) { st *= __expf(mt - l); mt = l; }
        st += __expf(l - mt);
    }
#pragma unroll
    for (int o = 16; o > 0; o >>= 1) {
        float mo = __shfl_xor_sync(0xffffffffu, mt, o);
        float so = __shfl_xor_sync(0xffffffffu, st, o);
        float pm = fmaxf(mt, mo);
        float a = (mt > NEG_INF) ? st * __expf(mt - pm) : 0.f;
        float b = (mo > NEG_INF) ? so * __expf(mo - pm) : 0.f;
        mt = pm; st = a + b;
    }
    float inv = 1.f / st;

    float4 acc = make_float4(0.f, 0.f, 0.f, 0.f);
    for (int base = 0; base < deg; base += 32) {
        int j = base + lane;
        int sj = 0; float cj = 0.f;
        if (j < deg) {
            sj = g_adj[off + j];
            cj = __expf(lrelu(g_es[sj] + edn) - mt);
        }
        int lim = min(32, deg - base);
#pragma unroll 4
        for (int it = 0; it < lim; it++) {
            int s    = __shfl_sync(0xffffffffu, sj, it);
            float cf = __shfl_sync(0xffffffffu, cj, it);
            float4 v = *(const float4*)(g_h + (size_t)s * C + lane * 4);
            acc.x = fmaf(cf, v.x, acc.x);
            acc.y = fmaf(cf, v.y, acc.y);
            acc.z = fmaf(cf, v.z, acc.z);
            acc.w = fmaf(cf, v.w, acc.w);
        }
    }
    float4 bg = *(const float4*)(b_gat + lane * 4);
    float4 o4 = make_float4(acc.x * inv + bg.x, acc.y * inv + bg.y,
                            acc.z * inv + bg.z, acc.w * inv + bg.w);
    *(float4*)(zout + (size_t)n * C + lane * 4) = o4;
}

// ---- decode: recon = tanh(z @ Wd + bd), NB=8, transposed float4 reads ----
__global__ void k_decode(const float* __restrict__ Wd, const float* __restrict__ bd,
                         float* __restrict__ out) {
    int nb = blockIdx.x * NB;
    int c = threadIdx.x;
    __shared__ float zs[C][NB];          // transposed: zs[k][i]
    const float* zbase = out + (size_t)N_NODES * C;
#pragma unroll
    for (int i = 0; i < NB; i++)
        zs[c][i] = zbase[(size_t)(nb + i) * C + c];
    __syncthreads();
    float b = bd[c];
    float acc[NB];
#pragma unroll
    for (int i = 0; i < NB; i++) acc[i] = b;
#pragma unroll 4
    for (int k = 0; k < C; k++) {
        float w = Wd[k * C + c];
        const float4 a0 = *(const float4*)&zs[k][0];
        const float4 a1 = *(const float4*)&zs[k][4];
        acc[0] = fmaf(a0.x, w, acc[0]);  acc[1] = fmaf(a0.y, w, acc[1]);
        acc[2] = fmaf(a0.z, w, acc[2]);  acc[3] = fmaf(a0.w, w, acc[3]);
        acc[4] = fmaf(a1.x, w, acc[4]);  acc[5] = fmaf(a1.y, w, acc[5]);
        acc[6] = fmaf(a1.z, w, acc[6]);  acc[7] = fmaf(a1.w, w, acc[7]);
    }
#pragma unroll
    for (int i = 0; i < NB; i++)
        out[(size_t)(nb + i) * C + c] = tanhf(acc[i]);
}

extern "C" void kernel_launch(void* const* d_in, const int* in_sizes, int n_in,
                              void* d_out, int out_size) {
    const float* x     = (const float*)d_in[0];
    const int*   ei    = (const int*)d_in[1];     // int32 (JAX x64 off)
    const float* W     = (const float*)d_in[2];
    const float* a_src = (const float*)d_in[3];
    const float* a_dst = (const float*)d_in[4];
    const float* b_gat = (const float*)d_in[5];
    const float* Wd    = (const float*)d_in[6];
    const float* bd    = (const float*)d_in[7];
    float* out  = (float*)d_out;
    float* zout = out + (size_t)N_NODES * C;

    k_zero<<<(N_NODES + 255) / 256, 256>>>();
    k_gemm_hist<<<GEMM_BLKS + HIST_BLKS, C>>>(x, W, a_src, a_dst, ei);
    k_scan1<<<NBLK, 1024>>>();
    k_scan3<<<NBLK, 1024>>>();
    {
        int threads = 256;
        int eblocks = (E_TOT + threads - 1) / threads;
        k_fill<<<eblocks, threads>>>(ei);
    }
    k_gather<<<N_NODES / 4, 128>>>(b_gat, zout);
    k_decode<<<N_NODES / NB, C>>>(Wd, bd, out);
}